// round 9
// baseline (speedup 1.0000x reference)
#include <cuda_runtime.h>
#include <cuda_bf16.h>

#define N_EXPERTS 48
#define D_IN 163840            // 2*1280*8*8
#define D_OUT 2
#define BATCH 512
#define THREADS 256
#define G 2                    // samples per group (same expert)
#define MAXG ((BATCH + N_EXPERTS) / G)   // 280 groups worst case
#define NSPLIT 16              // D_IN split
#define CHUNK (D_IN / NSPLIT)  // 10240 floats
#define N4 (CHUNK / 4)         // 2560 float4
#define ITERS (N4 / THREADS)   // 10
#define GRID_MAIN (MAXG * NSPLIT)   // 4480 CTAs
#define PREP_SEGS 4
#define SEG_LEN (BATCH / PREP_SEGS)  // 128

// ---- scratch (device globals: no allocation allowed) ----
__device__ int   g_group_expert[MAXG];
__device__ int   g_group_samples[MAXG * G];      // -1 = empty slot
__device__ float g_partials[BATCH * NSPLIT * 2];
__device__ int   g_count[BATCH];                 // per-sample split tickets
__device__ int   g_flag;                         // prep-done flag
__device__ int   g_exit;                         // CTA exit counter

// CTA 0: deterministic stable grouping of samples by expert (256 threads).
__device__ void do_prep(const int* __restrict__ t, int tid) {
    __shared__ int sh_e[BATCH];
    __shared__ int segbase[N_EXPERTS][PREP_SEGS];
    __shared__ int cnt[N_EXPERTS];
    __shared__ int gb[N_EXPERTS];
    __shared__ int rnk[BATCH];

    for (int j = tid; j < BATCH; j += THREADS) {
        int e = t[j] - 1;
        sh_e[j] = ((e % N_EXPERTS) + N_EXPERTS) % N_EXPERTS;
    }
    __syncthreads();

    // per-(expert, segment) counts
    if (tid < N_EXPERTS * PREP_SEGS) {
        const int ex = tid / PREP_SEGS, seg = tid % PREP_SEGS;
        int c = 0;
        for (int j = seg * SEG_LEN; j < seg * SEG_LEN + SEG_LEN; j++)
            c += (sh_e[j] == ex);
        segbase[ex][seg] = c;
    }
    __syncthreads();
    if (tid < N_EXPERTS) {
        int r = 0;
        #pragma unroll
        for (int s = 0; s < PREP_SEGS; s++) {
            int c = segbase[tid][s];
            segbase[tid][s] = r;
            r += c;
        }
        cnt[tid] = r;
    }
    __syncthreads();
    if (tid == 0) {
        int gsum = 0;
        for (int e2 = 0; e2 < N_EXPERTS; e2++) {
            gb[e2] = gsum;
            gsum += (cnt[e2] + G - 1) / G;
        }
    }
    // init group table
    for (int i = tid; i < MAXG * G; i += THREADS) g_group_samples[i] = -1;
    __syncthreads();
    // stable ranks
    if (tid < N_EXPERTS * PREP_SEGS) {
        const int ex = tid / PREP_SEGS, seg = tid % PREP_SEGS;
        int r = segbase[ex][seg];
        for (int j = seg * SEG_LEN; j < seg * SEG_LEN + SEG_LEN; j++)
            if (sh_e[j] == ex) rnk[j] = r++;
    }
    __syncthreads();
    for (int j = tid; j < BATCH; j += THREADS) {
        const int r = rnk[j], ee = sh_e[j];
        const int grp = gb[ee] + r / G;
        g_group_samples[grp * G + (r % G)] = j;
        if ((r % G) == 0) g_group_expert[grp] = ee;
    }
    __threadfence();
    __syncthreads();
    if (tid == 0) atomicExch(&g_flag, 1);   // release prep results
}

__global__ __launch_bounds__(THREADS, 6)
void moe_gemv_fused(const float* __restrict__ x,
                    const int* __restrict__ t,
                    const float* __restrict__ W,
                    const float* __restrict__ bias,
                    float* __restrict__ out) {
    const int grp   = blockIdx.x >> 4;          // NSPLIT = 16
    const int split = blockIdx.x & (NSPLIT - 1);
    const int tid   = threadIdx.x;

    if (blockIdx.x == 0) {
        do_prep(t, tid);
    } else {
        if (tid == 0) {
            while (atomicAdd(&g_flag, 0) == 0) __nanosleep(64);
            __threadfence();                    // acquire prep results
        }
        __syncthreads();
    }

    const int sA = g_group_samples[grp * G + 0];
    if (sA >= 0) {                              // skip empty group slots
        const int sB_raw = g_group_samples[grp * G + 1];
        const bool hasB = (sB_raw >= 0);
        const int sB = hasB ? sB_raw : sA;
        const int e  = g_group_expert[grp];

        const int base4 = split * N4;           // float4 offset in sample row
        const float4* __restrict__ x4 = reinterpret_cast<const float4*>(x);
        const float4* __restrict__ wv =
            reinterpret_cast<const float4*>(W + (size_t)e * D_IN * D_OUT) + 2 * base4;
        const int xiA = sA * (D_IN / 4) + base4;
        const int xiB = sB * (D_IN / 4) + base4;

        float a0 = 0.0f, a1 = 0.0f, b0 = 0.0f, b1 = 0.0f;

        #pragma unroll
        for (int k = 0; k < ITERS; k++) {
            const int i = tid + k * THREADS;
            const float4 xa = __ldcs(&x4[xiA + i]);   // stream, evict-first
            const float4 xb = __ldcs(&x4[xiB + i]);
            const float4 w0 = __ldg(&wv[2 * i]);      // plain 16B, L1+L2 cached
            const float4 w1 = __ldg(&wv[2 * i + 1]);
            a0 = fmaf(xa.x, w0.x, a0);  a1 = fmaf(xa.x, w0.y, a1);
            b0 = fmaf(xb.x, w0.x, b0);  b1 = fmaf(xb.x, w0.y, b1);
            a0 = fmaf(xa.y, w0.z, a0);  a1 = fmaf(xa.y, w0.w, a1);
            b0 = fmaf(xb.y, w0.z, b0);  b1 = fmaf(xb.y, w0.w, b1);
            a0 = fmaf(xa.z, w1.x, a0);  a1 = fmaf(xa.z, w1.y, a1);
            b0 = fmaf(xb.z, w1.x, b0);  b1 = fmaf(xb.z, w1.y, b1);
            a0 = fmaf(xa.w, w1.z, a0);  a1 = fmaf(xa.w, w1.w, a1);
            b0 = fmaf(xb.w, w1.z, b0);  b1 = fmaf(xb.w, w1.w, b1);
        }

        #pragma unroll
        for (int off = 16; off > 0; off >>= 1) {
            a0 += __shfl_down_sync(0xFFFFFFFFu, a0, off);
            a1 += __shfl_down_sync(0xFFFFFFFFu, a1, off);
            b0 += __shfl_down_sync(0xFFFFFFFFu, b0, off);
            b1 += __shfl_down_sync(0xFFFFFFFFu, b1, off);
        }

        __shared__ float s_red[THREADS / 32][4];
        const int warp = tid >> 5;
        const int lane = tid & 31;
        if (lane == 0) {
            s_red[warp][0] = a0; s_red[warp][1] = a1;
            s_red[warp][2] = b0; s_red[warp][3] = b1;
        }
        __syncthreads();

        if (tid == 0) {
            float f[4] = {0.0f, 0.0f, 0.0f, 0.0f};
            #pragma unroll
            for (int w = 0; w < THREADS / 32; w++) {
                f[0] += s_red[w][0]; f[1] += s_red[w][1];
                f[2] += s_red[w][2]; f[3] += s_red[w][3];
            }
            // Publish partials (unique slots -> deterministic)
            g_partials[(sA * NSPLIT + split) * 2 + 0] = f[0];
            g_partials[(sA * NSPLIT + split) * 2 + 1] = f[1];
            if (hasB) {
                g_partials[(sB * NSPLIT + split) * 2 + 0] = f[2];
                g_partials[(sB * NSPLIT + split) * 2 + 1] = f[3];
            }
            __threadfence();

            // Per-sample ticket; last arriver finishes (fixed-order sum).
            #pragma unroll
            for (int which = 0; which < 2; which++) {
                if (which == 1 && !hasB) break;
                const int s = (which == 0) ? sA : sB;
                int old = atomicAdd(&g_count[s], 1);
                if (old == NSPLIT - 1) {
                    g_count[s] = 0;             // reset for next graph replay
                    __threadfence();
                    volatile const float* p = g_partials + (size_t)s * NSPLIT * 2;
                    float o0 = 0.0f, o1 = 0.0f;
                    #pragma unroll 4
                    for (int sp = 0; sp < NSPLIT; sp++) {
                        o0 += p[2 * sp + 0];
                        o1 += p[2 * sp + 1];
                    }
                    out[2 * s + 0] = o0 + bias[2 * e + 0];
                    out[2 * s + 1] = o1 + bias[2 * e + 1];
                }
            }
        }
    }

    // Exit ticket: the LAST CTA (of all, incl. empty groups) resets prep
    // state for the next graph replay. Safe: flag is only cleared after every
    // CTA has passed its spin.
    __syncthreads();
    if (tid == 0) {
        int od = atomicAdd(&g_exit, 1);
        if (od == GRID_MAIN - 1) {
            g_exit = 0;
            g_flag = 0;
        }
    }
}

extern "C" void kernel_launch(void* const* d_in, const int* in_sizes, int n_in,
                              void* d_out, int out_size) {
    const float* x    = (const float*)d_in[0];  // [512, 2,1280,8,8] fp32
    const int*   t    = (const int*)d_in[1];    // [512] int32
    const float* W    = (const float*)d_in[2];  // [48, 163840, 2] fp32
    const float* bias = (const float*)d_in[3];  // [48, 2] fp32
    float* out = (float*)d_out;                 // [512, 2] fp32

    moe_gemv_fused<<<GRID_MAIN, THREADS>>>(x, t, W, bias, out);
}

// round 10
// speedup vs baseline: 1.1165x; 1.1165x over previous
#include <cuda_runtime.h>
#include <cuda_bf16.h>

#define N_EXPERTS 48
#define D_IN 163840            // 2*1280*8*8
#define D_OUT 2
#define BATCH 512
#define THREADS 256
#define G 2                    // samples per group (same expert)
#define MAXG ((BATCH + N_EXPERTS) / G)   // 280 groups worst case
#define NSPLIT 16              // D_IN split
#define CHUNK (D_IN / NSPLIT)  // 10240 floats
#define N4 (CHUNK / 4)         // 2560 float4
#define ITERS (N4 / THREADS)   // 10
#define GRID_MAIN (MAXG * NSPLIT)   // 4480 CTAs

// ---- scratch (device globals: no allocation allowed) ----
__device__ float g_partials[BATCH * NSPLIT * 2];
__device__ int   g_count[BATCH];   // per-sample split tickets (self-resetting)

__global__ __launch_bounds__(THREADS, 6)
void moe_gemv_grouped(const float* __restrict__ x,
                      const int* __restrict__ t,
                      const float* __restrict__ W,
                      const float* __restrict__ bias,
                      float* __restrict__ out) {
    const int grp   = blockIdx.x >> 4;          // NSPLIT = 16
    const int split = blockIdx.x & (NSPLIT - 1);
    const int tid   = threadIdx.x;
    const int warp  = tid >> 5;
    const int lane  = tid & 31;

    // ---------- per-CTA redundant grouping (no inter-CTA sync) ----------
    __shared__ int sh_hist[N_EXPERTS];
    __shared__ int sh_meta[4];        // emy, r0, ngroups, cntE
    __shared__ int sh_wsum[THREADS / 32];
    __shared__ int sh_pair[2];        // sA, sB

    if (tid < N_EXPERTS) sh_hist[tid] = 0;
    __syncthreads();

    // samples j0 = 2*tid, j1 = 2*tid+1 (contiguous order for stable ranks)
    const int j0 = 2 * tid, j1 = 2 * tid + 1;
    int e0 = t[j0] - 1; e0 = ((e0 % N_EXPERTS) + N_EXPERTS) % N_EXPERTS;
    int e1 = t[j1] - 1; e1 = ((e1 % N_EXPERTS) + N_EXPERTS) % N_EXPERTS;
    atomicAdd(&sh_hist[e0], 1);
    atomicAdd(&sh_hist[e1], 1);
    __syncthreads();

    if (tid == 0) {
        int base = 0, emy = -1, r0 = 0;
        #pragma unroll 4
        for (int e = 0; e < N_EXPERTS; e++) {
            const int c = sh_hist[e];
            const int g = (c + G - 1) / G;
            if (emy < 0 && grp < base + g) { emy = e; r0 = (grp - base) * G; }
            base += g;
        }
        sh_meta[0] = emy;
        sh_meta[1] = r0;
        sh_meta[2] = base;                      // total groups
        sh_meta[3] = (emy >= 0) ? sh_hist[emy] : 0;
    }
    __syncthreads();

    const int ngroups = sh_meta[2];
    if (grp >= ngroups) return;                 // empty group slot
    const int emy  = sh_meta[0];
    const int r0   = sh_meta[1];
    const int cntE = sh_meta[3];

    // locate the samples with stable ranks r0 and r0+1 for expert emy
    {
        const int m0 = (e0 == emy) ? 1 : 0;
        const int m1 = (e1 == emy) ? 1 : 0;
        int v = m0 + m1;                        // pair sum
        #pragma unroll
        for (int off = 1; off < 32; off <<= 1) {
            int n = __shfl_up_sync(0xFFFFFFFFu, v, off);
            if (lane >= off) v += n;
        }
        if (lane == 31) sh_wsum[warp] = v;
        __syncthreads();
        int wbase = 0;
        #pragma unroll
        for (int w = 0; w < THREADS / 32; w++)
            wbase += (w < warp) ? sh_wsum[w] : 0;
        const int excl0 = wbase + v - (m0 + m1);  // exclusive prefix at j0
        const int excl1 = excl0 + m0;             // exclusive prefix at j1
        if (m0 && excl0 == r0)     sh_pair[0] = j0;
        if (m0 && excl0 == r0 + 1) sh_pair[1] = j0;
        if (m1 && excl1 == r0)     sh_pair[0] = j1;
        if (m1 && excl1 == r0 + 1) sh_pair[1] = j1;
        __syncthreads();
    }

    const int sA   = sh_pair[0];
    const bool hasB = (r0 + 1 < cntE);
    const int sB   = hasB ? sh_pair[1] : sA;

    // ---------- grouped split-K mainloop (identical to R6-main) ----------
    const int base4 = split * N4;               // float4 offset in sample row
    const float4* __restrict__ x4 = reinterpret_cast<const float4*>(x);
    const float4* __restrict__ wv =
        reinterpret_cast<const float4*>(W + (size_t)emy * D_IN * D_OUT) + 2 * base4;
    const int xiA = sA * (D_IN / 4) + base4;
    const int xiB = sB * (D_IN / 4) + base4;

    float a0 = 0.0f, a1 = 0.0f, b0 = 0.0f, b1 = 0.0f;

    #pragma unroll
    for (int k = 0; k < ITERS; k++) {
        const int i = tid + k * THREADS;
        const float4 xa = __ldcs(&x4[xiA + i]);   // stream, evict-first
        const float4 xb = __ldcs(&x4[xiB + i]);
        const float4 w0 = __ldg(&wv[2 * i]);      // L1+L2 cached
        const float4 w1 = __ldg(&wv[2 * i + 1]);
        a0 = fmaf(xa.x, w0.x, a0);  a1 = fmaf(xa.x, w0.y, a1);
        b0 = fmaf(xb.x, w0.x, b0);  b1 = fmaf(xb.x, w0.y, b1);
        a0 = fmaf(xa.y, w0.z, a0);  a1 = fmaf(xa.y, w0.w, a1);
        b0 = fmaf(xb.y, w0.z, b0);  b1 = fmaf(xb.y, w0.w, b1);
        a0 = fmaf(xa.z, w1.x, a0);  a1 = fmaf(xa.z, w1.y, a1);
        b0 = fmaf(xb.z, w1.x, b0);  b1 = fmaf(xb.z, w1.y, b1);
        a0 = fmaf(xa.w, w1.z, a0);  a1 = fmaf(xa.w, w1.w, a1);
        b0 = fmaf(xb.w, w1.z, b0);  b1 = fmaf(xb.w, w1.w, b1);
    }

    #pragma unroll
    for (int off = 16; off > 0; off >>= 1) {
        a0 += __shfl_down_sync(0xFFFFFFFFu, a0, off);
        a1 += __shfl_down_sync(0xFFFFFFFFu, a1, off);
        b0 += __shfl_down_sync(0xFFFFFFFFu, b0, off);
        b1 += __shfl_down_sync(0xFFFFFFFFu, b1, off);
    }

    __shared__ float s_red[THREADS / 32][4];
    if (lane == 0) {
        s_red[warp][0] = a0; s_red[warp][1] = a1;
        s_red[warp][2] = b0; s_red[warp][3] = b1;
    }
    __syncthreads();

    if (tid == 0) {
        float f[4] = {0.0f, 0.0f, 0.0f, 0.0f};
        #pragma unroll
        for (int w = 0; w < THREADS / 32; w++) {
            f[0] += s_red[w][0]; f[1] += s_red[w][1];
            f[2] += s_red[w][2]; f[3] += s_red[w][3];
        }
        // Publish partials (unique slots -> deterministic)
        g_partials[(sA * NSPLIT + split) * 2 + 0] = f[0];
        g_partials[(sA * NSPLIT + split) * 2 + 1] = f[1];
        if (hasB) {
            g_partials[(sB * NSPLIT + split) * 2 + 0] = f[2];
            g_partials[(sB * NSPLIT + split) * 2 + 1] = f[3];
        }
        __threadfence();

        // Per-sample ticket; last arriver finishes (fixed-order sum).
        #pragma unroll
        for (int which = 0; which < 2; which++) {
            if (which == 1 && !hasB) break;
            const int s = (which == 0) ? sA : sB;
            int old = atomicAdd(&g_count[s], 1);
            if (old == NSPLIT - 1) {
                g_count[s] = 0;                 // reset for next graph replay
                __threadfence();
                volatile const float* p = g_partials + (size_t)s * NSPLIT * 2;
                float o0 = 0.0f, o1 = 0.0f;
                #pragma unroll 4
                for (int sp = 0; sp < NSPLIT; sp++) {
                    o0 += p[2 * sp + 0];
                    o1 += p[2 * sp + 1];
                }
                out[2 * s + 0] = o0 + bias[2 * emy + 0];
                out[2 * s + 1] = o1 + bias[2 * emy + 1];
            }
        }
    }
}

extern "C" void kernel_launch(void* const* d_in, const int* in_sizes, int n_in,
                              void* d_out, int out_size) {
    const float* x    = (const float*)d_in[0];  // [512, 2,1280,8,8] fp32
    const int*   t    = (const int*)d_in[1];    // [512] int32
    const float* W    = (const float*)d_in[2];  // [48, 163840, 2] fp32
    const float* bias = (const float*)d_in[3];  // [48, 2] fp32
    float* out = (float*)d_out;                 // [512, 2] fp32

    moe_gemv_grouped<<<GRID_MAIN, THREADS>>>(x, t, W, bias, out);
}